// round 4
// baseline (speedup 1.0000x reference)
#include <cuda_runtime.h>
#include <math.h>

// Problem: HardNegativeContrastiveLoss, B=8192, D=128, T=0.1, margin=0.5.
//
// Key identity: the reference does NOT mask the diagonal of neg_sim. For
// normalized rows, neg_sim[i][i] = 1/T, and all off-diagonal cosines are
// <= 1 (Cauchy-Schwarz), so hardest_neg[i] == 1/T exactly for ANY input.
// Therefore:
//   loss = mean over 2B of relu(1/T + margin - pos_sim_dup)
//        = (1/B) * sum_i relu(10.5 - dot(z1_i, z2_i)/(||z1_i||*||z2_i||))
// The O(B^2 D) GEMM vanishes; only an O(B D) streaming row reduction remains.

#define BB    8192
#define DD    128
#define NWARP 8          // warps per block
#define NBLK  (BB / NWARP)   // 1024 blocks, one warp per row

__device__ float g_partials[NBLK];

__global__ __launch_bounds__(NWARP * 32)
void hncl_rows(const float* __restrict__ z1, const float* __restrict__ z2) {
    const int row  = (blockIdx.x * (NWARP * 32) + threadIdx.x) >> 5;  // [0, 8192)
    const int lane = threadIdx.x & 31;

    // D=128 floats = 32 lanes x float4, fully coalesced 512B per warp per tensor
    const float4 a = reinterpret_cast<const float4*>(z1 + (size_t)row * DD)[lane];
    const float4 b = reinterpret_cast<const float4*>(z2 + (size_t)row * DD)[lane];

    float ss1 = a.x * a.x + a.y * a.y + a.z * a.z + a.w * a.w;
    float ss2 = b.x * b.x + b.y * b.y + b.z * b.z + b.w * b.w;
    float dp  = a.x * b.x + a.y * b.y + a.z * b.z + a.w * b.w;

    #pragma unroll
    for (int o = 16; o > 0; o >>= 1) {
        ss1 += __shfl_xor_sync(0xFFFFFFFFu, ss1, o);
        ss2 += __shfl_xor_sync(0xFFFFFFFFu, ss2, o);
        dp  += __shfl_xor_sync(0xFFFFFFFFu, dp,  o);
    }

    __shared__ float sacc[NWARP];
    if (lane == 0) {
        const float n1 = fmaxf(sqrtf(ss1), 1e-12f);
        const float n2 = fmaxf(sqrtf(ss2), 1e-12f);
        const float pos = dp / (n1 * n2);
        // hardest_neg = 1/T = 10.0 (unmasked diagonal); loss duplicated over 2B
        sacc[threadIdx.x >> 5] = fmaxf(10.0f + 0.5f - pos, 0.0f);
    }
    __syncthreads();

    if (threadIdx.x == 0) {
        float s = 0.0f;
        #pragma unroll
        for (int w = 0; w < NWARP; w++) s += sacc[w];
        g_partials[blockIdx.x] = s;
    }
}

__global__ __launch_bounds__(256)
void hncl_finalize(float* __restrict__ out) {
    const int t = threadIdx.x;
    // 1024 partials / 256 threads = 4 each
    float v = g_partials[t] + g_partials[t + 256] +
              g_partials[t + 512] + g_partials[t + 768];

    #pragma unroll
    for (int o = 16; o > 0; o >>= 1)
        v += __shfl_xor_sync(0xFFFFFFFFu, v, o);

    __shared__ float sacc[8];
    if ((t & 31) == 0) sacc[t >> 5] = v;
    __syncthreads();

    if (t == 0) {
        float s = 0.0f;
        #pragma unroll
        for (int w = 0; w < 8; w++) s += sacc[w];
        // mean over 2B of duplicated per-row losses == sum_i relu_i / B
        out[0] = s * (1.0f / (float)BB);
    }
}

extern "C" void kernel_launch(void* const* d_in, const int* in_sizes, int n_in,
                              void* d_out, int out_size) {
    const float* z1 = (const float*)d_in[0];
    const float* z2 = (const float*)d_in[1];
    float* out = (float*)d_out;
    (void)in_sizes; (void)n_in; (void)out_size;

    hncl_rows<<<NBLK, NWARP * 32>>>(z1, z2);
    hncl_finalize<<<1, 256>>>(out);
}

// round 7
// speedup vs baseline: 1.4709x; 1.4709x over previous
#include <cuda_runtime.h>
#include <math.h>

// HardNegativeContrastiveLoss, B=8192, D=128, T=0.1, margin=0.5.
//
// Identity (see R3): the reference leaves the diagonal of neg_sim unmasked,
// so hardest_neg[i] == 1/T exactly for any input. The O(B^2 D) GEMM vanishes:
//   loss = (1/B) * sum_i relu(10.5 - dot(z1_i,z2_i)/(||z1_i||*||z2_i||))
//
// R4: fuse the two-kernel reduction into ONE kernel (fenced last-block-done
// pattern) to kill the second-launch overhead that dominated the 16.2us time.

#define BB       8192
#define DD       128
#define THREADS  256
#define NBLK     256          // 8 warps/block * 4 rows/warp * 256 blocks = 8192 rows

__device__ float    g_partials[NBLK];
__device__ unsigned g_count;   // zero-initialized at load; last block resets to 0

__global__ __launch_bounds__(THREADS)
void hncl_fused(const float* __restrict__ z1, const float* __restrict__ z2,
                float* __restrict__ out) {
    const int lane  = threadIdx.x & 31;
    const int warp  = threadIdx.x >> 5;                 // 0..7
    const int wglob = blockIdx.x * 8 + warp;            // 0..2047
    const int row0  = wglob * 4;                        // 4 consecutive rows per warp

    // Issue all 8 float4 loads up front -> MLP=8 per lane, coalesced 512B/warp/row.
    float4 a[4], b[4];
    #pragma unroll
    for (int k = 0; k < 4; k++) {
        a[k] = reinterpret_cast<const float4*>(z1 + (size_t)(row0 + k) * DD)[lane];
        b[k] = reinterpret_cast<const float4*>(z2 + (size_t)(row0 + k) * DD)[lane];
    }

    float ss1[4], ss2[4], dp[4];
    #pragma unroll
    for (int k = 0; k < 4; k++) {
        ss1[k] = a[k].x*a[k].x + a[k].y*a[k].y + a[k].z*a[k].z + a[k].w*a[k].w;
        ss2[k] = b[k].x*b[k].x + b[k].y*b[k].y + b[k].z*b[k].z + b[k].w*b[k].w;
        dp[k]  = a[k].x*b[k].x + a[k].y*b[k].y + a[k].z*b[k].z + a[k].w*b[k].w;
    }

    #pragma unroll
    for (int o = 16; o > 0; o >>= 1) {
        #pragma unroll
        for (int k = 0; k < 4; k++) {
            ss1[k] += __shfl_xor_sync(0xFFFFFFFFu, ss1[k], o);
            ss2[k] += __shfl_xor_sync(0xFFFFFFFFu, ss2[k], o);
            dp[k]  += __shfl_xor_sync(0xFFFFFFFFu, dp[k],  o);
        }
    }

    __shared__ float sacc[8];
    if (lane == 0) {
        float s = 0.0f;
        #pragma unroll
        for (int k = 0; k < 4; k++) {
            const float n1 = fmaxf(sqrtf(ss1[k]), 1e-12f);
            const float n2 = fmaxf(sqrtf(ss2[k]), 1e-12f);
            s += fmaxf(10.5f - dp[k] / (n1 * n2), 0.0f);
        }
        sacc[warp] = s;
    }
    __syncthreads();

    __shared__ unsigned s_is_last;
    if (threadIdx.x == 0) {
        float s = 0.0f;
        #pragma unroll
        for (int w = 0; w < 8; w++) s += sacc[w];
        g_partials[blockIdx.x] = s;
        __threadfence();                               // partial visible before count
        const unsigned done = atomicAdd(&g_count, 1u);
        s_is_last = (done == NBLK - 1) ? 1u : 0u;
    }
    __syncthreads();

    if (s_is_last) {
        // Final 256-element reduce by the last block (deterministic order).
        float v = g_partials[threadIdx.x];
        #pragma unroll
        for (int o = 16; o > 0; o >>= 1)
            v += __shfl_xor_sync(0xFFFFFFFFu, v, o);

        __shared__ float fin[8];
        if (lane == 0) fin[warp] = v;
        __syncthreads();

        if (threadIdx.x == 0) {
            float s = 0.0f;
            #pragma unroll
            for (int w = 0; w < 8; w++) s += fin[w];
            out[0] = s * (1.0f / (float)BB);
            g_count = 0;                               // reset for next graph replay
        }
    }
}

extern "C" void kernel_launch(void* const* d_in, const int* in_sizes, int n_in,
                              void* d_out, int out_size) {
    const float* z1 = (const float*)d_in[0];
    const float* z2 = (const float*)d_in[1];
    float* out = (float*)d_out;
    (void)in_sizes; (void)n_in; (void)out_size;

    hncl_fused<<<NBLK, THREADS>>>(z1, z2, out);
}

// round 8
// speedup vs baseline: 1.8672x; 1.2694x over previous
#include <cuda_runtime.h>
#include <math.h>

// HardNegativeContrastiveLoss, B=8192, D=128, T=0.1, margin=0.5.
//
// Identity (R3): the reference leaves the diagonal of neg_sim unmasked, so
// hardest_neg[i] == 1/T exactly for any input. The O(B^2 D) GEMM vanishes:
//   loss = (1/B) * sum_i relu(10.5 - dot(z1_i,z2_i)/(||z1_i||*||z2_i||))
//
// R7: R4's fused kernel was latency-bound (occ 19%, DRAM 10%). Go wide:
// one row per warp, 1024 blocks -> 8192 warps (~55/SM, single wave).

#define BB       8192
#define DD       128
#define THREADS  256
#define NBLK     1024         // 8 warps/block * 1 row/warp * 1024 blocks = 8192 rows

__device__ float    g_partials[NBLK];
__device__ unsigned g_count;   // zero-init at load; last block resets to 0

__global__ __launch_bounds__(THREADS)
void hncl_fused(const float* __restrict__ z1, const float* __restrict__ z2,
                float* __restrict__ out) {
    const int lane = threadIdx.x & 31;
    const int warp = threadIdx.x >> 5;                  // 0..7
    const int row  = blockIdx.x * 8 + warp;             // 0..8191

    // D=128 floats = 32 lanes x float4: two coalesced 512B loads per warp.
    const float4 a = reinterpret_cast<const float4*>(z1 + (size_t)row * DD)[lane];
    const float4 b = reinterpret_cast<const float4*>(z2 + (size_t)row * DD)[lane];

    float ss1 = a.x*a.x + a.y*a.y + a.z*a.z + a.w*a.w;
    float ss2 = b.x*b.x + b.y*b.y + b.z*b.z + b.w*b.w;
    float dp  = a.x*b.x + a.y*b.y + a.z*b.z + a.w*b.w;

    #pragma unroll
    for (int o = 16; o > 0; o >>= 1) {
        ss1 += __shfl_xor_sync(0xFFFFFFFFu, ss1, o);
        ss2 += __shfl_xor_sync(0xFFFFFFFFu, ss2, o);
        dp  += __shfl_xor_sync(0xFFFFFFFFu, dp,  o);
    }

    __shared__ float sacc[8];
    if (lane == 0) {
        const float n1 = fmaxf(sqrtf(ss1), 1e-12f);
        const float n2 = fmaxf(sqrtf(ss2), 1e-12f);
        sacc[warp] = fmaxf(10.5f - dp / (n1 * n2), 0.0f);
    }
    __syncthreads();

    __shared__ unsigned s_is_last;
    if (threadIdx.x == 0) {
        float s = 0.0f;
        #pragma unroll
        for (int w = 0; w < 8; w++) s += sacc[w];
        g_partials[blockIdx.x] = s;
        __threadfence();                                // partial visible before count
        const unsigned done = atomicAdd(&g_count, 1u);
        s_is_last = (done == NBLK - 1) ? 1u : 0u;
    }
    __syncthreads();

    if (s_is_last) {
        // Last block reduces the 1024 partials (deterministic order).
        const int t = threadIdx.x;
        float v = g_partials[t] + g_partials[t + 256] +
                  g_partials[t + 512] + g_partials[t + 768];

        #pragma unroll
        for (int o = 16; o > 0; o >>= 1)
            v += __shfl_xor_sync(0xFFFFFFFFu, v, o);

        __shared__ float fin[8];
        if (lane == 0) fin[warp] = v;
        __syncthreads();

        if (t == 0) {
            float s = 0.0f;
            #pragma unroll
            for (int w = 0; w < 8; w++) s += fin[w];
            out[0] = s * (1.0f / (float)BB);
            g_count = 0;                                // reset for next graph replay
        }
    }
}

extern "C" void kernel_launch(void* const* d_in, const int* in_sizes, int n_in,
                              void* d_out, int out_size) {
    const float* z1 = (const float*)d_in[0];
    const float* z2 = (const float*)d_in[1];
    float* out = (float*)d_out;
    (void)in_sizes; (void)n_in; (void)out_size;

    hncl_fused<<<NBLK, THREADS>>>(z1, z2, out);
}